// round 16
// baseline (speedup 1.0000x reference)
#include <cuda_runtime.h>
#include <cuda_fp16.h>
#include <cstdint>

#define ROWSTRIDE 5248
#define NTILES    1312
#define GRIDSZ    148
#define NTHREADS  512
#define SMEM_BYTES 131072

#define BUFSTR 65536u
#define O_W    32768u

// Pre-converted W image: per s: 3 chunks x 32768 B (fp16, pre-swizzled)
#define WPRE_PER_S 98304
__device__ __align__(16) unsigned char g_wpre[41 * WPRE_PER_S];

static __device__ __forceinline__ uint32_t smem_u32(const void* p) {
    uint32_t a;
    asm("{ .reg .u64 t; cvta.to.shared.u64 t, %1; cvt.u32.u64 %0, t; }"
        : "=r"(a) : "l"(p));
    return a;
}
static __device__ __forceinline__ void ldsm4(uint32_t* r, uint32_t a) {
    asm volatile("ldmatrix.sync.aligned.m8n8.x4.shared.b16 {%0,%1,%2,%3}, [%4];"
                 : "=r"(r[0]), "=r"(r[1]), "=r"(r[2]), "=r"(r[3]) : "r"(a));
}
static __device__ __forceinline__ void ldsm4t(uint32_t* r, uint32_t a) {
    asm volatile("ldmatrix.sync.aligned.m8n8.x4.trans.shared.b16 {%0,%1,%2,%3}, [%4];"
                 : "=r"(r[0]), "=r"(r[1]), "=r"(r[2]), "=r"(r[3]) : "r"(a));
}
static __device__ __forceinline__ void mma_f16(float* c, const uint32_t* a, const uint32_t* b) {
    asm volatile("mma.sync.aligned.m16n8k16.row.col.f32.f16.f16.f32 "
                 "{%0,%1,%2,%3}, {%4,%5,%6,%7}, {%8,%9}, {%0,%1,%2,%3};"
                 : "+f"(c[0]), "+f"(c[1]), "+f"(c[2]), "+f"(c[3])
                 : "r"(a[0]), "r"(a[1]), "r"(a[2]), "r"(a[3]), "r"(b[0]), "r"(b[1]));
}
static __device__ __forceinline__ uint32_t cvt2h(float a, float b) {
    return (uint32_t)__half_as_ushort(__float2half_rn(a)) |
           ((uint32_t)__half_as_ushort(__float2half_rn(b)) << 16);
}
static __device__ __forceinline__ void cp16(uint32_t dst, const void* src) {
    asm volatile("cp.async.cg.shared.global [%0], [%1], 16;"
                 :: "r"(dst), "l"(src) : "memory");
}

// ------------- precompute: W fp32 -> swizzled fp16 image --------------------
__global__ void __launch_bounds__(256)
wsplit_kernel(const float* __restrict__ W) {
    const int step = gridDim.x * blockDim.x;
    const int TOT = 41 * 12288;                      // float4 count
    for (int v = blockIdx.x * blockDim.x + threadIdx.x; v < TOT; v += step) {
        const int s = v / 12288, rem = v % 12288;
        const int k = rem >> 5, q = rem & 31;        // k 0..383, q = float4-in-row
        const float4 w = *(const float4*)(W + (size_t)v * 4);
        const int c = k >> 7, kr = k & 127;          // 3 chunks of 128 k-rows
        const size_t d = (size_t)s * WPRE_PER_S + (size_t)c * 32768
                       + (size_t)kr * 256
                       + ((((uint32_t)(q >> 1)) ^ ((uint32_t)kr & 7u)) << 4)
                       + (uint32_t)((q & 1) << 3);
        *(uint2*)(g_wpre + d) = make_uint2(cvt2h(w.x, w.y), cvt2h(w.z, w.w));
    }
}

// ------------------------------ main kernel --------------------------------
__global__ void __launch_bounds__(NTHREADS, 1)
poslin_kernel(const float* __restrict__ x,
              const float* __restrict__ bias, float* __restrict__ out)
{
    extern __shared__ __align__(128) char smem[];
    const uint32_t sb = smem_u32(smem);
    const int tid  = threadIdx.x;
    const int lane = tid & 31;
    const int wid  = tid >> 5;                 // 0..15

    const int start = (int)(((long)blockIdx.x * NTILES) / GRIDSZ);
    const int end   = (int)(((long)(blockIdx.x + 1) * NTILES) / GRIDSZ);
    const int Ctot  = (end - start) * 3;       // 3 K128-chunks per tile

    if (wid < 8) {
        // == PRODUCER (8 warps, wid 0-7: LOW arbiter priority by design) =====
        const int ptid = tid;                        // 0..255
        const int xq = ptid & 31, xr0 = ptid >> 5;   // f4-in-row (0..31), row base 0..7
        const uint32_t xCvt = ((((uint32_t)(xq >> 1)) ^ ((uint32_t)xr0 & 7u)) << 4)
                            + (uint32_t)((xq & 1) << 3);

        int tL = start, cL = 0;

#define FILL(bufv) do {                                                         \
    const int s_ = tL >> 5, mt_ = tL & 31, bb_ = mt_ << 7;                      \
    const int e_ = (s_ - 1 + cL) * 128 + xq * 4;                                \
    const bool v_ = (e_ >= 0) && (e_ < ROWSTRIDE);                              \
    const uint32_t bo_ = (uint32_t)(bufv) * BUFSTR;                             \
    /* W fp16 32KB pre-swizzled: 8 x 16B per thread */                          \
    {                                                                           \
        const unsigned char* wsrc = g_wpre + (size_t)s_ * WPRE_PER_S            \
                                  + (size_t)cL * 32768 + (size_t)ptid * 16;     \
        const uint32_t wdst = sb + bo_ + O_W + (uint32_t)ptid * 16u;            \
        _Pragma("unroll")                                                       \
        for (int i = 0; i < 8; ++i)                                             \
            cp16(wdst + (uint32_t)(i * 4096), wsrc + (size_t)i * 4096);         \
        asm volatile("cp.async.commit_group;" ::: "memory");                    \
    }                                                                           \
    /* x: 16 float4 LDG (batched), fp16 cvt + STS */                            \
    float4 xa[16];                                                              \
    _Pragma("unroll")                                                           \
    for (int it = 0; it < 16; ++it)                                             \
        xa[it] = v_ ? *(const float4*)(x + (size_t)(bb_ + xr0 + 8*it) * ROWSTRIDE + e_) \
                    : make_float4(0.f, 0.f, 0.f, 0.f);                          \
    _Pragma("unroll")                                                           \
    for (int it = 0; it < 16; ++it) {                                           \
        uint32_t o_ = bo_ + (uint32_t)(xr0 + 8*it) * 256u + xCvt;               \
        *(uint2*)(smem + o_) = make_uint2(cvt2h(xa[it].x, xa[it].y),            \
                                          cvt2h(xa[it].z, xa[it].w));           \
    }                                                                           \
    asm volatile("cp.async.wait_group 0;" ::: "memory");                        \
} while (0)

        FILL(0);
        if (++cL == 3) { cL = 0; ++tL; }
        for (int g = 0; g < Ctot; ++g) {
            __syncthreads();
            if (g + 1 < Ctot) {
                FILL((g + 1) & 1);
                if (++cL == 3) { cL = 0; ++tL; }
            }
        }
#undef FILL
    } else {
        // == CONSUMER (8 warps, wid 8-15: HIGH arbiter priority), 64x32 tile =
        const int cwid = wid - 8;              // 0..7
        const int m0 = (cwid >> 2) << 6;       // 0, 64
        const int n0 = (cwid & 3) << 5;        // 0, 32, 64, 96
        const int g8 = lane >> 2, tig = lane & 3;
        // same-SMSP consumer pairs are (cwid, cwid+4): stagger by bit2
        const int ksoff = ((cwid >> 2) & 1) << 2;

        const uint32_t aRowB = (uint32_t)(m0 + (lane & 15));
        const uint32_t aKC   = (uint32_t)(lane >> 4);
        const uint32_t l7    = (uint32_t)(lane & 7);
        const uint32_t bKrB  = (uint32_t)(lane & 15);
        const uint32_t bNCB  = (uint32_t)((n0 >> 3) + (lane >> 4));

        int t = start, c = 0;
        float acc[4][4][4];                    // [i: m16 block][j: n8][4]

        for (int g = 0; g < Ctot; ++g) {
            __syncthreads();
            if (c == 0) {
                _Pragma("unroll")
                for (int i = 0; i < 4; ++i)
                    _Pragma("unroll")
                    for (int j = 0; j < 4; ++j)
                        _Pragma("unroll")
                        for (int u = 0; u < 4; ++u) acc[i][j][u] = 0.f;
            }
            {
                const uint32_t Ab = sb + (uint32_t)(g & 1) * BUFSTR;
                _Pragma("unroll")
                for (int ks2 = 0; ks2 < 8; ++ks2) {
                    const int ks = (ks2 + ksoff) & 7;
                    uint32_t ah[4][4];
                    _Pragma("unroll")
                    for (int i = 0; i < 4; ++i) {
                        uint32_t ad = Ab + (aRowB + 16u*i) * 256u
                                    + ((((uint32_t)(ks * 2) + aKC) ^ l7) << 4);
                        ldsm4(ah[i], ad);
                    }
                    _Pragma("unroll")
                    for (int jj = 0; jj < 2; ++jj) {
                        uint32_t bd = Ab + O_W + (bKrB + 16u*ks) * 256u
                                    + (((bNCB + 2u*jj) ^ l7) << 4);
                        uint32_t bh_[4];
                        ldsm4t(bh_, bd);
                        _Pragma("unroll")
                        for (int i = 0; i < 4; ++i) {
                            mma_f16(acc[i][2*jj],     ah[i], bh_);
                            mma_f16(acc[i][2*jj + 1], ah[i], bh_ + 2);
                        }
                    }
                }
            }
            if (c == 2) {
                const int s = t >> 5, bbase = (t & 31) << 7;
                const float* brow = bias + s * 128;
                _Pragma("unroll")
                for (int j = 0; j < 4; ++j) {
                    const int n = n0 + 8 * j + 2 * tig;
                    const float b0 = brow[n], b1 = brow[n + 1];
                    _Pragma("unroll")
                    for (int i = 0; i < 4; ++i) {
                        const size_t rb = (size_t)(bbase + m0 + 16 * i + g8) * ROWSTRIDE
                                        + (size_t)s * 128 + n;
                        float2 v0, v1;
                        v0.x = fmaxf(acc[i][j][0] + b0, 0.f);
                        v0.y = fmaxf(acc[i][j][1] + b1, 0.f);
                        v1.x = fmaxf(acc[i][j][2] + b0, 0.f);
                        v1.y = fmaxf(acc[i][j][3] + b1, 0.f);
                        *(float2*)(out + rb)                 = v0;
                        *(float2*)(out + rb + 8 * ROWSTRIDE) = v1;
                    }
                }
            }
            if (++c == 3) { c = 0; ++t; }
        }
    }
}

extern "C" void kernel_launch(void* const* d_in, const int* in_sizes, int n_in,
                              void* d_out, int out_size) {
    const float* x = (const float*)d_in[0];
    const float* W = (const float*)d_in[1];
    const float* b = (const float*)d_in[2];
    float* out = (float*)d_out;
    wsplit_kernel<<<296, 256>>>(W);
    cudaFuncSetAttribute(poslin_kernel,
                         cudaFuncAttributeMaxDynamicSharedMemorySize, SMEM_BYTES);
    poslin_kernel<<<GRIDSZ, NTHREADS, SMEM_BYTES>>>(x, b, out);
}